// round 11
// baseline (speedup 1.0000x reference)
#include <cuda_runtime.h>
#include <cstdint>
#include <cstddef>

// ============================================================================
// MLP_SAT v3.1: factorized edge-MLP + segment mean.
//   prep_kernel: W2/W3 -> global scratch in mma-fragment k-pair layout (tf32)
//   gemm_LC (merged): L = l_embs@W1a + b1 ; C = c_embs@W1b   (tf32 mma)
//   edge_kernel: 128 edges/block, 3 CTAs/SM, 16-channel chunked pipelined
//                layer-2; B-fragments LDG'd from L2-resident scratch.
//   v3.1 fix: first smem region sized for BOTH h1c [128][20] and its h3
//             [128][25] reuse (3200 words) — v3 overflowed h3 into h2 (race).
// ============================================================================

#define NLITS 131072
#define NCLS  65536

__device__ float g_L[(size_t)NLITS * 256];
__device__ float g_C[(size_t)NCLS * 256];
__device__ float g_sums[NCLS];
__device__ float g_cnts[NCLS];
__device__ unsigned g_W2p[16384];   // ((k8*64+n)*4+t4)*2+th ; k = k8*8+th*4+t4
__device__ unsigned g_W3p[1536];    // ((k8*24+n)*4+t4)*2+th ; n padded 20->24

__device__ __forceinline__ unsigned f2tf(float x) {
    unsigned r;
    asm("cvt.rna.tf32.f32 %0, %1;" : "=r"(r) : "f"(x));
    return r;
}

__device__ __forceinline__ void mma_tf32(float* d, const unsigned* a, const unsigned* b) {
    asm volatile(
        "mma.sync.aligned.m16n8k8.row.col.f32.tf32.tf32.f32 "
        "{%0,%1,%2,%3}, {%4,%5,%6,%7}, {%8,%9}, {%0,%1,%2,%3};\n"
        : "+f"(d[0]), "+f"(d[1]), "+f"(d[2]), "+f"(d[3])
        : "r"(a[0]), "r"(a[1]), "r"(a[2]), "r"(a[3]), "r"(b[0]), "r"(b[1]));
}

// ----------------------------------------------------------------------------
// One-time weight repack into fragment-coalesced tf32 layout.
// ----------------------------------------------------------------------------
__global__ void prep_kernel(const float* __restrict__ W2,
                            const float* __restrict__ W3) {
    int idx = blockIdx.x * blockDim.x + threadIdx.x;
    if (idx < 16384) {
        int k = idx >> 6, n = idx & 63;
        int k8 = k >> 3, t4 = k & 3, th = (k >> 2) & 1;
        g_W2p[((k8 * 64 + n) * 4 + t4) * 2 + th] = f2tf(W2[k * 64 + n]);
    }
    if (idx < 1536) {
        int th = idx & 1, t4 = (idx >> 1) & 3, r = idx >> 3;  // r = k8*24+n
        int k8 = r / 24, n = r % 24;
        int k = k8 * 8 + th * 4 + t4;
        g_W3p[idx] = f2tf((n < 20) ? W3[k * 20 + n] : 0.f);
    }
}

// ----------------------------------------------------------------------------
// Merged GEMM: rows [0,nL) -> g_L = l_embs@W1[0:384]+b1 ; rows [nL,nL+nC) ->
// g_C = c_embs@W1[384:768]. BM=128,BN=128,BK=32; operands pre-cvt to tf32.
// ----------------------------------------------------------------------------
__global__ __launch_bounds__(256) void gemm_LC(
    const float* __restrict__ l_embs, const float* __restrict__ c_embs,
    const float* __restrict__ W1, const float* __restrict__ b1, int nL)
{
    __shared__ unsigned As[128 * 36];
    __shared__ unsigned Ws[32 * 132];

    const int tid  = threadIdx.x;
    const int warp = tid >> 5, lane = tid & 31;
    const int g = lane >> 2, t4 = lane & 3;
    const int wm = warp & 3, wn = warp >> 2;
    const int rowBase = blockIdx.x * 128;
    const int colBase = blockIdx.y * 128;

    const bool isL = rowBase < nL;
    const float* __restrict__ A = isL ? l_embs + (size_t)rowBase * 384
                                      : c_embs + (size_t)(rowBase - nL) * 384;
    const float* __restrict__ W = isL ? W1 : W1 + (size_t)384 * 256;
    float* __restrict__ out = isL ? g_L + (size_t)rowBase * 256
                                  : g_C + (size_t)(rowBase - nL) * 256;

    float acc[2][8][4];
    #pragma unroll
    for (int mi = 0; mi < 2; mi++)
        #pragma unroll
        for (int ni = 0; ni < 8; ni++)
            #pragma unroll
            for (int q = 0; q < 4; q++) acc[mi][ni][q] = 0.f;

    for (int kt = 0; kt < 384; kt += 32) {
        #pragma unroll
        for (int s = 0; s < 4; s++) {
            int slot = tid + s * 256;
            int r = slot >> 3, c = slot & 7;
            float4 v = *(const float4*)&A[(size_t)r * 384 + kt + c * 4];
            uint4 u = {f2tf(v.x), f2tf(v.y), f2tf(v.z), f2tf(v.w)};
            *(uint4*)&As[r * 36 + c * 4] = u;
        }
        #pragma unroll
        for (int s = 0; s < 4; s++) {
            int slot = tid + s * 256;
            int r = slot >> 5, c = slot & 31;
            float4 v = *(const float4*)&W[(size_t)(kt + r) * 256 + colBase + c * 4];
            uint4 u = {f2tf(v.x), f2tf(v.y), f2tf(v.z), f2tf(v.w)};
            *(uint4*)&Ws[r * 132 + c * 4] = u;
        }
        __syncthreads();

        #pragma unroll
        for (int k8 = 0; k8 < 4; k8++) {
            const int kc = k8 * 8;
            unsigned afr[2][4];
            #pragma unroll
            for (int mi = 0; mi < 2; mi++) {
                int rb = wm * 32 + mi * 16;
                afr[mi][0] = As[(rb + g    ) * 36 + kc + t4    ];
                afr[mi][1] = As[(rb + g + 8) * 36 + kc + t4    ];
                afr[mi][2] = As[(rb + g    ) * 36 + kc + t4 + 4];
                afr[mi][3] = As[(rb + g + 8) * 36 + kc + t4 + 4];
            }
            #pragma unroll
            for (int ni = 0; ni < 8; ni++) {
                unsigned bfr[2];
                int col = wn * 64 + ni * 8 + g;
                bfr[0] = Ws[(kc + t4    ) * 132 + col];
                bfr[1] = Ws[(kc + t4 + 4) * 132 + col];
                mma_tf32(acc[0][ni], afr[0], bfr);
                mma_tf32(acc[1][ni], afr[1], bfr);
            }
        }
        __syncthreads();
    }

    #pragma unroll
    for (int mi = 0; mi < 2; mi++) {
        #pragma unroll
        for (int ni = 0; ni < 8; ni++) {
            int r0 = wm * 32 + mi * 16 + g;
            int c0 = colBase + wn * 64 + ni * 8 + t4 * 2;
            float bb0 = isL ? b1[c0]     : 0.f;
            float bb1 = isL ? b1[c0 + 1] : 0.f;
            float2 v0 = {acc[mi][ni][0] + bb0, acc[mi][ni][1] + bb1};
            float2 v1 = {acc[mi][ni][2] + bb0, acc[mi][ni][3] + bb1};
            *(float2*)&out[(size_t)r0 * 256 + c0] = v0;
            *(float2*)&out[(size_t)(r0 + 8) * 256 + c0] = v1;
        }
    }
}

// ----------------------------------------------------------------------------
__global__ void zero_kernel(int n) {
    int i = blockIdx.x * blockDim.x + threadIdx.x;
    if (i < n) { g_sums[i] = 0.f; g_cnts[i] = 0.f; }
}

// ----------------------------------------------------------------------------
// Edge kernel v3.1: 128 edges/block, 256 threads, 3 CTAs/SM.
// smem (u32): region0 [3200] = h1c[128][20] chunk buf, reused as h3[128][25]
//             h2[128][68] | biases | idx
// W2/W3 B-fragments come straight from g_W2p/g_W3p (L2-resident).
// ----------------------------------------------------------------------------
#define EK_R0_WORDS   3200                     // max(128*20, 128*25)
#define EK_SMEM_WORDS (EK_R0_WORDS + 128*68 + 64 + 24 + 20 + 4 + 256)
#define EK_SMEM_BYTES (EK_SMEM_WORDS * 4)

__global__ __launch_bounds__(256, 3) void edge_kernel(
    const int* __restrict__ edge_i, const int* __restrict__ edge_j,
    const float* __restrict__ b2, const float* __restrict__ b3,
    const float* __restrict__ W4, const float* __restrict__ b4,
    int nE)
{
    extern __shared__ unsigned smu[];
    unsigned* h1c = smu;                    // region0: 3200 words
    unsigned* h2  = h1c + EK_R0_WORDS;      // 128*68
    float* b2s = (float*)(h2 + 128 * 68);   // 64
    float* b3s = b2s + 64;                  // 24
    float* W4s = b3s + 24;                  // 20
    float* b4s = W4s + 20;                  // 4
    int*   eis = (int*)(b4s + 4);           // 128
    int*   ejs = eis + 128;                 // 128
    float* h3  = (float*)h1c;               // [128][25] reuse of region0

    const int tid  = threadIdx.x;
    const int warp = tid >> 5, lane = tid & 31;
    const int g = lane >> 2, t4 = lane & 3;
    const int wm = warp & 3, wn = warp >> 2;     // 4m x 2n warp grid
    const int ebase = blockIdx.x * 128;

    if (tid < 64) b2s[tid] = b2[tid];
    if (tid < 24) b3s[tid] = (tid < 20) ? b3[tid] : 0.f;
    if (tid < 20) W4s[tid] = W4[tid];
    if (tid == 0) b4s[0] = b4[0];
    if (tid < 128) {
        int ge = ebase + tid;
        eis[tid] = (ge < nE) ? edge_i[ge] : 0;
        ejs[tid] = (ge < nE) ? edge_j[ge] : 0;
    }
    __syncthreads();

    // ---- layer 2: K chunked by 16, gather pipelined against mma ----
    float acc[2][4][4];
    #pragma unroll
    for (int mi = 0; mi < 2; mi++)
        #pragma unroll
        for (int ni = 0; ni < 4; ni++)
            #pragma unroll
            for (int q = 0; q < 4; q++) acc[mi][ni][q] = 0.f;

    const int e0 = tid >> 2,         q0 = (tid & 3) * 4;
    const int e1 = (tid + 256) >> 2, q1 = (tid & 3) * 4;
    const size_t rowL0 = (size_t)eis[e0] * 256, rowC0 = (size_t)ejs[e0] * 256;
    const size_t rowL1 = (size_t)eis[e1] * 256, rowC1 = (size_t)ejs[e1] * 256;

    float4 Lr[2], Cr[2];
    Lr[0] = *(const float4*)&g_L[rowL0 + q0];
    Cr[0] = *(const float4*)&g_C[rowC0 + q0];
    Lr[1] = *(const float4*)&g_L[rowL1 + q1];
    Cr[1] = *(const float4*)&g_C[rowC1 + q1];

    for (int c = 0; c < 16; c++) {
        // deposit chunk c: relu(L+C) -> tf32 into h1c
        uint4 hv0, hv1;
        hv0.x = f2tf(fmaxf(Lr[0].x + Cr[0].x, 0.f));
        hv0.y = f2tf(fmaxf(Lr[0].y + Cr[0].y, 0.f));
        hv0.z = f2tf(fmaxf(Lr[0].z + Cr[0].z, 0.f));
        hv0.w = f2tf(fmaxf(Lr[0].w + Cr[0].w, 0.f));
        hv1.x = f2tf(fmaxf(Lr[1].x + Cr[1].x, 0.f));
        hv1.y = f2tf(fmaxf(Lr[1].y + Cr[1].y, 0.f));
        hv1.z = f2tf(fmaxf(Lr[1].z + Cr[1].z, 0.f));
        hv1.w = f2tf(fmaxf(Lr[1].w + Cr[1].w, 0.f));
        *(uint4*)&h1c[e0 * 20 + q0] = hv0;
        *(uint4*)&h1c[e1 * 20 + q1] = hv1;
        __syncthreads();

        // prefetch chunk c+1 while mma runs
        if (c < 15) {
            int kk = (c + 1) * 16;
            Lr[0] = *(const float4*)&g_L[rowL0 + kk + q0];
            Cr[0] = *(const float4*)&g_C[rowC0 + kk + q0];
            Lr[1] = *(const float4*)&g_L[rowL1 + kk + q1];
            Cr[1] = *(const float4*)&g_C[rowC1 + kk + q1];
        }

        // mma over this 16-channel chunk (2 k8 steps)
        #pragma unroll
        for (int k8 = 0; k8 < 2; k8++) {
            const int kc = k8 * 8;
            unsigned a[2][4];
            #pragma unroll
            for (int mi = 0; mi < 2; mi++) {
                int rb = wm * 32 + mi * 16;
                a[mi][0] = h1c[(rb + g    ) * 20 + kc + t4    ];
                a[mi][1] = h1c[(rb + g + 8) * 20 + kc + t4    ];
                a[mi][2] = h1c[(rb + g    ) * 20 + kc + t4 + 4];
                a[mi][3] = h1c[(rb + g + 8) * 20 + kc + t4 + 4];
            }
            const int k8g = c * 2 + k8;
            #pragma unroll
            for (int ni = 0; ni < 4; ni++) {
                int col = wn * 32 + ni * 8 + g;
                uint2 bp = *(const uint2*)&g_W2p[((k8g * 64 + col) * 4 + t4) * 2];
                unsigned b[2] = {bp.x, bp.y};
                mma_tf32(acc[0][ni], a[0], b);
                mma_tf32(acc[1][ni], a[1], b);
            }
        }
        __syncthreads();
    }

    // ---- layer-2 epilogue: h2 = relu(acc + b2) as tf32 ----
    #pragma unroll
    for (int mi = 0; mi < 2; mi++) {
        #pragma unroll
        for (int ni = 0; ni < 4; ni++) {
            int row0 = wm * 32 + mi * 16 + g;
            int col  = wn * 32 + ni * 8 + t4 * 2;
            float bb0 = b2s[col], bb1 = b2s[col + 1];
            h2[ row0      * 68 + col    ] = f2tf(fmaxf(acc[mi][ni][0] + bb0, 0.f));
            h2[ row0      * 68 + col + 1] = f2tf(fmaxf(acc[mi][ni][1] + bb1, 0.f));
            h2[(row0 + 8) * 68 + col    ] = f2tf(fmaxf(acc[mi][ni][2] + bb0, 0.f));
            h2[(row0 + 8) * 68 + col + 1] = f2tf(fmaxf(acc[mi][ni][3] + bb1, 0.f));
        }
    }
    __syncthreads();

    // ---- layer 3: h3[128,24] = relu(h2[128,64] @ W3p + b3); all 8 warps ----
    {
        const int rb3 = warp * 16;
        float a3[3][4];
        #pragma unroll
        for (int ni = 0; ni < 3; ni++)
            #pragma unroll
            for (int q = 0; q < 4; q++) a3[ni][q] = 0.f;

        #pragma unroll
        for (int k8 = 0; k8 < 8; k8++) {
            const int kc = k8 * 8;
            unsigned a[4];
            a[0] = h2[(rb3 + g    ) * 68 + kc + t4    ];
            a[1] = h2[(rb3 + g + 8) * 68 + kc + t4    ];
            a[2] = h2[(rb3 + g    ) * 68 + kc + t4 + 4];
            a[3] = h2[(rb3 + g + 8) * 68 + kc + t4 + 4];
            #pragma unroll
            for (int ni = 0; ni < 3; ni++) {
                int col = ni * 8 + g;
                uint2 bp = *(const uint2*)&g_W3p[((k8 * 24 + col) * 4 + t4) * 2];
                unsigned b[2] = {bp.x, bp.y};
                mma_tf32(a3[ni], a, b);
            }
        }
        #pragma unroll
        for (int ni = 0; ni < 3; ni++) {
            int col = ni * 8 + t4 * 2;
            float bb0 = b3s[col], bb1 = b3s[col + 1];
            h3[(rb3 + g    ) * 25 + col    ] = fmaxf(a3[ni][0] + bb0, 0.f);
            h3[(rb3 + g    ) * 25 + col + 1] = fmaxf(a3[ni][1] + bb1, 0.f);
            h3[(rb3 + g + 8) * 25 + col    ] = fmaxf(a3[ni][2] + bb0, 0.f);
            h3[(rb3 + g + 8) * 25 + col + 1] = fmaxf(a3[ni][3] + bb1, 0.f);
        }
    }
    __syncthreads();

    // ---- layer 4 + per-clause atomic accumulation ----
    if (tid < 128) {
        int ge = ebase + tid;
        if (ge < nE) {
            float w = b4s[0];
            #pragma unroll
            for (int j = 0; j < 20; j++) w += h3[tid * 25 + j] * W4s[j];
            int cl = ejs[tid];
            atomicAdd(&g_sums[cl], w);
            atomicAdd(&g_cnts[cl], 1.0f);
        }
    }
}

// ----------------------------------------------------------------------------
__global__ void finalize_kernel(const int* __restrict__ edge_j,
                                float* __restrict__ out, int nE) {
    int e = blockIdx.x * blockDim.x + threadIdx.x;
    if (e < nE) {
        int j = edge_j[e];
        out[e] = g_sums[j] / fmaxf(g_cnts[j], 1.0f);
    }
}

// ----------------------------------------------------------------------------
extern "C" void kernel_launch(void* const* d_in, const int* in_sizes, int n_in,
                              void* d_out, int out_size)
{
    const float* l_embs = (const float*)d_in[0];
    const float* c_embs = (const float*)d_in[1];
    const int*   edge_i = (const int*)d_in[2];
    const int*   edge_j = (const int*)d_in[3];
    const float* W1     = (const float*)d_in[4];
    const float* b1     = (const float*)d_in[5];
    const float* W2     = (const float*)d_in[6];
    const float* b2     = (const float*)d_in[7];
    const float* W3     = (const float*)d_in[8];
    const float* b3     = (const float*)d_in[9];
    const float* W4     = (const float*)d_in[10];
    const float* b4     = (const float*)d_in[11];
    float* out = (float*)d_out;

    const int nL = in_sizes[0] / 384;   // 131072
    const int nC = in_sizes[1] / 384;   // 65536
    const int nE = in_sizes[2];         // 524288

    cudaFuncSetAttribute(edge_kernel,
                         cudaFuncAttributeMaxDynamicSharedMemorySize,
                         EK_SMEM_BYTES);

    prep_kernel<<<64, 256>>>(W2, W3);
    gemm_LC<<<dim3((nL + nC) / 128, 2), 256>>>(l_embs, c_embs, W1, b1, nL);
    zero_kernel<<<(nC + 255) / 256, 256>>>(nC);
    edge_kernel<<<(nE + 127) / 128, 256, EK_SMEM_BYTES>>>(
        edge_i, edge_j, b2, b3, W4, b4, nE);
    finalize_kernel<<<(nE + 255) / 256, 256>>>(edge_j, out, nE);
}

// round 12
// speedup vs baseline: 1.1036x; 1.1036x over previous
#include <cuda_runtime.h>
#include <cstdint>
#include <cstddef>

// ============================================================================
// MLP_SAT v4: factorized edge-MLP + segment mean.
//   prep_kernel: W1/W2/W3 -> global scratch in mma-fragment k-pair layout
//   gemm_LC: A-tile register-prefetch; B-fragments direct LDG from g_W1p
//            (no W staging, no W smem). Math order identical to v3.1.
//   edge_kernel: double-buffered h1c chunks -> ONE bar per chunk.
// ============================================================================

#define NLITS 131072
#define NCLS  65536

__device__ float g_L[(size_t)NLITS * 256];
__device__ float g_C[(size_t)NCLS * 256];
__device__ float g_sums[NCLS];
__device__ float g_cnts[NCLS];
__device__ unsigned g_W1p[196608];  // [h][k8<48][n<256][t4][th]; k=k8*8+th*4+t4
__device__ unsigned g_W2p[16384];   // ((k8*64+n)*4+t4)*2+th
__device__ unsigned g_W3p[1536];    // ((k8*24+n)*4+t4)*2+th ; n padded 20->24

__device__ __forceinline__ unsigned f2tf(float x) {
    unsigned r;
    asm("cvt.rna.tf32.f32 %0, %1;" : "=r"(r) : "f"(x));
    return r;
}

__device__ __forceinline__ void mma_tf32(float* d, const unsigned* a, const unsigned* b) {
    asm volatile(
        "mma.sync.aligned.m16n8k8.row.col.f32.tf32.tf32.f32 "
        "{%0,%1,%2,%3}, {%4,%5,%6,%7}, {%8,%9}, {%0,%1,%2,%3};\n"
        : "+f"(d[0]), "+f"(d[1]), "+f"(d[2]), "+f"(d[3])
        : "r"(a[0]), "r"(a[1]), "r"(a[2]), "r"(a[3]), "r"(b[0]), "r"(b[1]));
}

// ----------------------------------------------------------------------------
// One-time weight repack into fragment-coalesced tf32 layouts.
// ----------------------------------------------------------------------------
__global__ void prep_kernel(const float* __restrict__ W1,
                            const float* __restrict__ W2,
                            const float* __restrict__ W3) {
    int idx = blockIdx.x * blockDim.x + threadIdx.x;
    if (idx < 196608) {                       // W1: 768 x 256
        int n = idx & 255, k = idx >> 8;      // k in 0..767
        int h = (k >= 384) ? 1 : 0;
        int kl = k - h * 384;
        int k8 = kl >> 3, t4 = kl & 3, th = (kl >> 2) & 1;
        g_W1p[(((h * 48 + k8) * 256 + n) * 4 + t4) * 2 + th] = f2tf(W1[k * 256 + n]);
    }
    if (idx < 16384) {                        // W2: 256 x 64
        int k = idx >> 6, n = idx & 63;
        int k8 = k >> 3, t4 = k & 3, th = (k >> 2) & 1;
        g_W2p[((k8 * 64 + n) * 4 + t4) * 2 + th] = f2tf(W2[k * 64 + n]);
    }
    if (idx < 1536) {                         // W3: 64 x 20 (pad to 24)
        int th = idx & 1, t4 = (idx >> 1) & 3, r = idx >> 3;  // r = k8*24+n
        int k8 = r / 24, n = r % 24;
        int k = k8 * 8 + th * 4 + t4;
        g_W3p[idx] = f2tf((n < 20) ? W3[k * 20 + n] : 0.f);
    }
}

// ----------------------------------------------------------------------------
// Merged GEMM: rows [0,nL) -> g_L = l_embs@W1[0:384]+b1 ; rows [nL,nL+nC) ->
// g_C = c_embs@W1[384:768]. BM=128, BN=128, BK=32. A-tile reg-prefetch;
// B fragments LDG'd directly from g_W1p (L2-hot). No W smem/staging.
// ----------------------------------------------------------------------------
__global__ __launch_bounds__(256) void gemm_LC(
    const float* __restrict__ l_embs, const float* __restrict__ c_embs,
    const float* __restrict__ b1, int nL)
{
    __shared__ unsigned As[128 * 36];

    const int tid  = threadIdx.x;
    const int warp = tid >> 5, lane = tid & 31;
    const int g = lane >> 2, t4 = lane & 3;
    const int wm = warp & 3, wn = warp >> 2;
    const int rowBase = blockIdx.x * 128;
    const int colBase = blockIdx.y * 128;

    const bool isL = rowBase < nL;
    const float* __restrict__ A = isL ? l_embs + (size_t)rowBase * 384
                                      : c_embs + (size_t)(rowBase - nL) * 384;
    const unsigned* __restrict__ Wp = g_W1p + (isL ? 0 : 48 * 256 * 8);
    float* __restrict__ out = isL ? g_L + (size_t)rowBase * 256
                                  : g_C + (size_t)(rowBase - nL) * 256;

    // per-thread A staging coords: 4 slots of 1024 float4s
    const int ar = tid >> 1;                  // rows covered by slots (see below)
    (void)ar;

    float acc[2][8][4];
    #pragma unroll
    for (int mi = 0; mi < 2; mi++)
        #pragma unroll
        for (int ni = 0; ni < 8; ni++)
            #pragma unroll
            for (int q = 0; q < 4; q++) acc[mi][ni][q] = 0.f;

    float4 pA[4];
    #pragma unroll
    for (int s = 0; s < 4; s++) {             // prefetch kt=0
        int slot = tid + s * 256;
        int r = slot >> 3, c = slot & 7;
        pA[s] = *(const float4*)&A[(size_t)r * 384 + c * 4];
    }

    for (int kt = 0; kt < 12; kt++) {
        #pragma unroll
        for (int s = 0; s < 4; s++) {         // deposit staged A tile (cvt tf32)
            int slot = tid + s * 256;
            int r = slot >> 3, c = slot & 7;
            uint4 u = {f2tf(pA[s].x), f2tf(pA[s].y), f2tf(pA[s].z), f2tf(pA[s].w)};
            *(uint4*)&As[r * 36 + c * 4] = u;
        }
        __syncthreads();

        if (kt < 11) {                        // prefetch next tile under mma
            #pragma unroll
            for (int s = 0; s < 4; s++) {
                int slot = tid + s * 256;
                int r = slot >> 3, c = slot & 7;
                pA[s] = *(const float4*)&A[(size_t)r * 384 + (kt + 1) * 32 + c * 4];
            }
        }

        #pragma unroll
        for (int k8 = 0; k8 < 4; k8++) {
            const int kc = k8 * 8;
            const int k8g = kt * 4 + k8;
            unsigned afr[2][4];
            #pragma unroll
            for (int mi = 0; mi < 2; mi++) {
                int rb = wm * 32 + mi * 16;
                afr[mi][0] = As[(rb + g    ) * 36 + kc + t4    ];
                afr[mi][1] = As[(rb + g + 8) * 36 + kc + t4    ];
                afr[mi][2] = As[(rb + g    ) * 36 + kc + t4 + 4];
                afr[mi][3] = As[(rb + g + 8) * 36 + kc + t4 + 4];
            }
            #pragma unroll
            for (int ni = 0; ni < 8; ni++) {
                int col = colBase + wn * 64 + ni * 8 + g;
                uint2 bp = *(const uint2*)&Wp[((size_t)(k8g * 256 + col) * 4 + t4) * 2];
                unsigned b[2] = {bp.x, bp.y};
                mma_tf32(acc[0][ni], afr[0], b);
                mma_tf32(acc[1][ni], afr[1], b);
            }
        }
        __syncthreads();
    }

    #pragma unroll
    for (int mi = 0; mi < 2; mi++) {
        #pragma unroll
        for (int ni = 0; ni < 8; ni++) {
            int r0 = wm * 32 + mi * 16 + g;
            int c0 = colBase + wn * 64 + ni * 8 + t4 * 2;
            float bb0 = isL ? b1[c0]     : 0.f;
            float bb1 = isL ? b1[c0 + 1] : 0.f;
            float2 v0 = {acc[mi][ni][0] + bb0, acc[mi][ni][1] + bb1};
            float2 v1 = {acc[mi][ni][2] + bb0, acc[mi][ni][3] + bb1};
            *(float2*)&out[(size_t)r0 * 256 + c0] = v0;
            *(float2*)&out[(size_t)(r0 + 8) * 256 + c0] = v1;
        }
    }
}

// ----------------------------------------------------------------------------
__global__ void zero_kernel(int n) {
    int i = blockIdx.x * blockDim.x + threadIdx.x;
    if (i < n) { g_sums[i] = 0.f; g_cnts[i] = 0.f; }
}

// ----------------------------------------------------------------------------
// Edge kernel v4: 128 edges/block, 256 threads, 3 CTAs/SM.
// Double-buffered h1c (2 x 128x20) -> ONE __syncthreads per chunk.
// Region0 [5120] also hosts the h3[128][25] reuse (3200 words).
// ----------------------------------------------------------------------------
#define EK_R0_WORDS   5120                     // 2*2560 >= 3200 (h3 reuse)
#define EK_SMEM_WORDS (EK_R0_WORDS + 128*68 + 64 + 24 + 20 + 4 + 256)
#define EK_SMEM_BYTES (EK_SMEM_WORDS * 4)

__global__ __launch_bounds__(256, 3) void edge_kernel(
    const int* __restrict__ edge_i, const int* __restrict__ edge_j,
    const float* __restrict__ b2, const float* __restrict__ b3,
    const float* __restrict__ W4, const float* __restrict__ b4,
    int nE)
{
    extern __shared__ unsigned smu[];
    unsigned* h1a = smu;                    // 2560
    unsigned* h1b = smu + 2560;             // 2560
    unsigned* h2  = smu + EK_R0_WORDS;      // 128*68
    float* b2s = (float*)(h2 + 128 * 68);   // 64
    float* b3s = b2s + 64;                  // 24
    float* W4s = b3s + 24;                  // 20
    float* b4s = W4s + 20;                  // 4
    int*   eis = (int*)(b4s + 4);           // 128
    int*   ejs = eis + 128;                 // 128
    float* h3  = (float*)smu;               // [128][25] reuse of region0

    const int tid  = threadIdx.x;
    const int warp = tid >> 5, lane = tid & 31;
    const int g = lane >> 2, t4 = lane & 3;
    const int wm = warp & 3, wn = warp >> 2;     // 4m x 2n warp grid
    const int ebase = blockIdx.x * 128;

    if (tid < 64) b2s[tid] = b2[tid];
    if (tid < 24) b3s[tid] = (tid < 20) ? b3[tid] : 0.f;
    if (tid < 20) W4s[tid] = W4[tid];
    if (tid == 0) b4s[0] = b4[0];
    if (tid < 128) {
        int ge = ebase + tid;
        eis[tid] = (ge < nE) ? edge_i[ge] : 0;
        ejs[tid] = (ge < nE) ? edge_j[ge] : 0;
    }
    __syncthreads();

    // ---- layer 2: K chunked by 16, double-buffered, one bar per chunk ----
    float acc[2][4][4];
    #pragma unroll
    for (int mi = 0; mi < 2; mi++)
        #pragma unroll
        for (int ni = 0; ni < 4; ni++)
            #pragma unroll
            for (int q = 0; q < 4; q++) acc[mi][ni][q] = 0.f;

    const int e0 = tid >> 2,         q0 = (tid & 3) * 4;
    const int e1 = (tid + 256) >> 2, q1 = (tid & 3) * 4;
    const size_t rowL0 = (size_t)eis[e0] * 256, rowC0 = (size_t)ejs[e0] * 256;
    const size_t rowL1 = (size_t)eis[e1] * 256, rowC1 = (size_t)ejs[e1] * 256;

    float4 Lr[2], Cr[2];
    Lr[0] = *(const float4*)&g_L[rowL0 + q0];
    Cr[0] = *(const float4*)&g_C[rowC0 + q0];
    Lr[1] = *(const float4*)&g_L[rowL1 + q1];
    Cr[1] = *(const float4*)&g_C[rowC1 + q1];

    for (int c = 0; c < 16; c++) {
        unsigned* buf = (c & 1) ? h1b : h1a;

        // deposit chunk c: relu(L+C) -> tf32
        uint4 hv0, hv1;
        hv0.x = f2tf(fmaxf(Lr[0].x + Cr[0].x, 0.f));
        hv0.y = f2tf(fmaxf(Lr[0].y + Cr[0].y, 0.f));
        hv0.z = f2tf(fmaxf(Lr[0].z + Cr[0].z, 0.f));
        hv0.w = f2tf(fmaxf(Lr[0].w + Cr[0].w, 0.f));
        hv1.x = f2tf(fmaxf(Lr[1].x + Cr[1].x, 0.f));
        hv1.y = f2tf(fmaxf(Lr[1].y + Cr[1].y, 0.f));
        hv1.z = f2tf(fmaxf(Lr[1].z + Cr[1].z, 0.f));
        hv1.w = f2tf(fmaxf(Lr[1].w + Cr[1].w, 0.f));
        *(uint4*)&buf[e0 * 20 + q0] = hv0;
        *(uint4*)&buf[e1 * 20 + q1] = hv1;
        __syncthreads();                    // deposits of c visible to all

        if (c < 15) {                       // prefetch next chunk under mma
            int kk = (c + 1) * 16;
            Lr[0] = *(const float4*)&g_L[rowL0 + kk + q0];
            Cr[0] = *(const float4*)&g_C[rowC0 + kk + q0];
            Lr[1] = *(const float4*)&g_L[rowL1 + kk + q1];
            Cr[1] = *(const float4*)&g_C[rowC1 + kk + q1];
        }

        #pragma unroll
        for (int k8 = 0; k8 < 2; k8++) {
            const int kc = k8 * 8;
            unsigned a[2][4];
            #pragma unroll
            for (int mi = 0; mi < 2; mi++) {
                int rb = wm * 32 + mi * 16;
                a[mi][0] = buf[(rb + g    ) * 20 + kc + t4    ];
                a[mi][1] = buf[(rb + g + 8) * 20 + kc + t4    ];
                a[mi][2] = buf[(rb + g    ) * 20 + kc + t4 + 4];
                a[mi][3] = buf[(rb + g + 8) * 20 + kc + t4 + 4];
            }
            const int k8g = c * 2 + k8;
            #pragma unroll
            for (int ni = 0; ni < 4; ni++) {
                int col = wn * 32 + ni * 8 + g;
                uint2 bp = *(const uint2*)&g_W2p[((k8g * 64 + col) * 4 + t4) * 2];
                unsigned b[2] = {bp.x, bp.y};
                mma_tf32(acc[0][ni], a[0], b);
                mma_tf32(acc[1][ni], a[1], b);
            }
        }
        // no second bar: next deposit targets the other buffer; buf_c is only
        // rewritten at c+2, fenced by the bar at c+1 (every warp passes it
        // only after finishing mma(c)).
    }

    // ---- layer-2 epilogue: h2 = relu(acc + b2) as tf32 ----
    #pragma unroll
    for (int mi = 0; mi < 2; mi++) {
        #pragma unroll
        for (int ni = 0; ni < 4; ni++) {
            int row0 = wm * 32 + mi * 16 + g;
            int col  = wn * 32 + ni * 8 + t4 * 2;
            float bb0 = b2s[col], bb1 = b2s[col + 1];
            h2[ row0      * 68 + col    ] = f2tf(fmaxf(acc[mi][ni][0] + bb0, 0.f));
            h2[ row0      * 68 + col + 1] = f2tf(fmaxf(acc[mi][ni][1] + bb1, 0.f));
            h2[(row0 + 8) * 68 + col    ] = f2tf(fmaxf(acc[mi][ni][2] + bb0, 0.f));
            h2[(row0 + 8) * 68 + col + 1] = f2tf(fmaxf(acc[mi][ni][3] + bb1, 0.f));
        }
    }
    __syncthreads();   // all mma done (program order) + h2 visible

    // ---- layer 3: h3[128,24] = relu(h2[128,64] @ W3p + b3); all 8 warps ----
    {
        const int rb3 = warp * 16;
        float a3[3][4];
        #pragma unroll
        for (int ni = 0; ni < 3; ni++)
            #pragma unroll
            for (int q = 0; q < 4; q++) a3[ni][q] = 0.f;

        #pragma unroll
        for (int k8 = 0; k8 < 8; k8++) {
            const int kc = k8 * 8;
            unsigned a[4];
            a[0] = h2[(rb3 + g    ) * 68 + kc + t4    ];
            a[1] = h2[(rb3 + g + 8) * 68 + kc + t4    ];
            a[2] = h2[(rb3 + g    ) * 68 + kc + t4 + 4];
            a[3] = h2[(rb3 + g + 8) * 68 + kc + t4 + 4];
            #pragma unroll
            for (int ni = 0; ni < 3; ni++) {
                int col = ni * 8 + g;
                uint2 bp = *(const uint2*)&g_W3p[((k8 * 24 + col) * 4 + t4) * 2];
                unsigned b[2] = {bp.x, bp.y};
                mma_tf32(a3[ni], a, b);
            }
        }
        #pragma unroll
        for (int ni = 0; ni < 3; ni++) {
            int col = ni * 8 + t4 * 2;
            float bb0 = b3s[col], bb1 = b3s[col + 1];
            h3[(rb3 + g    ) * 25 + col    ] = fmaxf(a3[ni][0] + bb0, 0.f);
            h3[(rb3 + g    ) * 25 + col + 1] = fmaxf(a3[ni][1] + bb1, 0.f);
            h3[(rb3 + g + 8) * 25 + col    ] = fmaxf(a3[ni][2] + bb0, 0.f);
            h3[(rb3 + g + 8) * 25 + col + 1] = fmaxf(a3[ni][3] + bb1, 0.f);
        }
    }
    __syncthreads();

    // ---- layer 4 + per-clause atomic accumulation ----
    if (tid < 128) {
        int ge = ebase + tid;
        if (ge < nE) {
            float w = b4s[0];
            #pragma unroll
            for (int j = 0; j < 20; j++) w += h3[tid * 25 + j] * W4s[j];
            int cl = ejs[tid];
            atomicAdd(&g_sums[cl], w);
            atomicAdd(&g_cnts[cl], 1.0f);
        }
    }
}

// ----------------------------------------------------------------------------
__global__ void finalize_kernel(const int* __restrict__ edge_j,
                                float* __restrict__ out, int nE) {
    int e = blockIdx.x * blockDim.x + threadIdx.x;
    if (e < nE) {
        int j = edge_j[e];
        out[e] = g_sums[j] / fmaxf(g_cnts[j], 1.0f);
    }
}

// ----------------------------------------------------------------------------
extern "C" void kernel_launch(void* const* d_in, const int* in_sizes, int n_in,
                              void* d_out, int out_size)
{
    const float* l_embs = (const float*)d_in[0];
    const float* c_embs = (const float*)d_in[1];
    const int*   edge_i = (const int*)d_in[2];
    const int*   edge_j = (const int*)d_in[3];
    const float* W1     = (const float*)d_in[4];
    const float* b1     = (const float*)d_in[5];
    const float* W2     = (const float*)d_in[6];
    const float* b2     = (const float*)d_in[7];
    const float* W3     = (const float*)d_in[8];
    const float* b3     = (const float*)d_in[9];
    const float* W4     = (const float*)d_in[10];
    const float* b4     = (const float*)d_in[11];
    float* out = (float*)d_out;

    const int nL = in_sizes[0] / 384;   // 131072
    const int nC = in_sizes[1] / 384;   // 65536
    const int nE = in_sizes[2];         // 524288

    cudaFuncSetAttribute(edge_kernel,
                         cudaFuncAttributeMaxDynamicSharedMemorySize,
                         EK_SMEM_BYTES);

    prep_kernel<<<768, 256>>>(W1, W2, W3);
    gemm_LC<<<dim3((nL + nC) / 128, 2), 256>>>(l_embs, c_embs, b1, nL);
    zero_kernel<<<(nC + 255) / 256, 256>>>(nC);
    edge_kernel<<<(nE + 127) / 128, 256, EK_SMEM_BYTES>>>(
        edge_i, edge_j, b2, b3, W4, b4, nE);
    finalize_kernel<<<(nE + 255) / 256, 256>>>(edge_j, out, nE);
}